// round 13
// baseline (speedup 1.0000x reference)
#include <cuda_runtime.h>
#include <math.h>
#include <stdint.h>

#define B 32
#define S 4096
#define H 1024
#define WARPS_PER_BLOCK 8
#define THREADS (WARPS_PER_BLOCK * 32)          // 256
#define BLOCKS_PER_BATCH 9
#define NBLOCKS (B * BLOCKS_PER_BATCH)          // 288
#define WARPS_PER_BATCH (BLOCKS_PER_BATCH * WARPS_PER_BLOCK)  // 72
#define ROWS_LO 57
#define ROWS_HI_START 64
#define ROW_BYTES (H * 4)                       // 4096
#define SLOTS 3
#define SMEM_BYTES (WARPS_PER_BLOCK * SLOTS * ROW_BYTES)   // 98304

// Scratch (__device__ globals; no dynamic allocation allowed)
__device__ float4 g_ctx_partial[B * WARPS_PER_BATCH * (H / 4)];  // 9.4 MB
__device__ float  g_m_partial[B * WARPS_PER_BATCH];
__device__ float  g_l_partial[B * WARPS_PER_BATCH];
__device__ unsigned int g_cnt[B];        // per-batch arrival counters (epoch via %9)

#define CP_ASYNC16(dst, src) \
    asm volatile("cp.async.cg.shared.global [%0], [%1], 16;" :: "r"(dst), "l"(src) : "memory")
#define CP_COMMIT() asm volatile("cp.async.commit_group;" ::: "memory")
#define CP_WAIT(n)  asm volatile("cp.async.wait_group %0;" :: "n"(n) : "memory")

// prefetch one full key row (4KB) into an smem slot; one commit group
__device__ __forceinline__ void prefetch_row(uint32_t sdst, const float* gsrc, int lane)
{
#pragma unroll
    for (int j = 0; j < 8; ++j)
        CP_ASYNC16(sdst + (uint32_t)(lane + 32 * j) * 16u,
                   gsrc + (size_t)(lane + 32 * j) * 4);
    CP_COMMIT();
}

// ---------------------------------------------------------------------------
// Phase 1: streaming with a per-warp 3-slot cp.async pipeline (loads decoupled
// from registers; DMA fills the shfl/exp latency bubbles).
// Phase 2: last-arriving block of each batch finalizes that batch (R12).
// ---------------------------------------------------------------------------
__global__ __launch_bounds__(THREADS, 2)
void attn_fused(const float* __restrict__ query,
                const float* __restrict__ keys,
                float* __restrict__ out_ctx,
                float* __restrict__ out_weights)
{
    extern __shared__ float4 s_kv[];    // [8 warps][3 slots][256 float4]

    const int w    = threadIdx.x >> 5;
    const int lane = threadIdx.x & 31;
    const int b    = blockIdx.x / BLOCKS_PER_BATCH;
    const int jblk = blockIdx.x % BLOCKS_PER_BATCH;
    const int i    = jblk * WARPS_PER_BLOCK + w;        // slot 0..71
    const int start = i * 56 + (i < ROWS_HI_START ? i : ROWS_HI_START);
    const int count = (i < ROWS_HI_START) ? ROWS_LO : 56;

    // ======================== Phase 1: streaming ========================
    {
        const float4* q4 = reinterpret_cast<const float4*>(query + (size_t)b * H);
        float4 qv[8];
#pragma unroll
        for (int j = 0; j < 8; ++j) qv[j] = q4[lane + 32 * j];

        float4 acc[8];
#pragma unroll
        for (int j = 0; j < 8; ++j) acc[j] = make_float4(0.f, 0.f, 0.f, 0.f);
        float m = -INFINITY;
        float l = 0.f;

        const float* krows = keys + ((size_t)b * S + start) * H;
        float* wout = out_weights + (size_t)b * S + start;

        // per-warp smem ring base (byte address in shared space)
        float4* ring = s_kv + (size_t)w * SLOTS * (H / 4);
        const uint32_t ring_u32 =
            (uint32_t)__cvta_generic_to_shared(ring);

        // prologue: prefetch rows 0,1
        prefetch_row(ring_u32 + 0 * ROW_BYTES, krows, lane);
        prefetch_row(ring_u32 + 1 * ROW_BYTES, krows + (size_t)H, lane);

        int slot = 0;
        for (int r = 0; r < count; ++r) {
            if (r < count - 1) { CP_WAIT(1); } else { CP_WAIT(0); }

            const float4* srow = ring + slot * (H / 4);
            float4 kv[8];
#pragma unroll
            for (int j = 0; j < 8; ++j) kv[j] = srow[lane + 32 * j];

            // prefetch row r+2 into the slot after next (held row r-1, consumed)
            if (r + 2 < count) {
                int ps = slot + 2; if (ps >= SLOTS) ps -= SLOTS;
                prefetch_row(ring_u32 + (uint32_t)ps * ROW_BYTES,
                             krows + (size_t)(r + 2) * H, lane);
            }

            float d = 0.f;
#pragma unroll
            for (int j = 0; j < 8; ++j) {
                d = fmaf(qv[j].x, kv[j].x, d);
                d = fmaf(qv[j].y, kv[j].y, d);
                d = fmaf(qv[j].z, kv[j].z, d);
                d = fmaf(qv[j].w, kv[j].w, d);
            }
#pragma unroll
            for (int o = 16; o > 0; o >>= 1)
                d += __shfl_xor_sync(0xFFFFFFFFu, d, o);

            if (lane == 0) wout[r] = d;

            float p;
            if (d > m) {                       // warp-uniform branch
                float scale = __expf(m - d);   // first iter: exp(-inf)=0
#pragma unroll
                for (int j = 0; j < 8; ++j) {
                    acc[j].x *= scale; acc[j].y *= scale;
                    acc[j].z *= scale; acc[j].w *= scale;
                }
                l = fmaf(l, scale, 1.f);
                m = d;
                p = 1.f;
            } else {
                p = __expf(d - m);
                l += p;
            }
#pragma unroll
            for (int j = 0; j < 8; ++j) {
                acc[j].x = fmaf(p, kv[j].x, acc[j].x);
                acc[j].y = fmaf(p, kv[j].y, acc[j].y);
                acc[j].z = fmaf(p, kv[j].z, acc[j].z);
                acc[j].w = fmaf(p, kv[j].w, acc[j].w);
            }

            if (++slot == SLOTS) slot = 0;
        }

        const int pslot = b * WARPS_PER_BATCH + i;
        float4* dst = &g_ctx_partial[(size_t)pslot * (H / 4)];
#pragma unroll
        for (int j = 0; j < 8; ++j) dst[lane + 32 * j] = acc[j];
        if (lane == 0) {
            g_m_partial[pslot] = m;
            g_l_partial[pslot] = l;
        }
    }

    // =============== arrival: am I the last block of batch b? ===============
    __shared__ unsigned int s_last;
    __syncthreads();
    if (threadIdx.x == 0) {
        __threadfence();                                 // release my partials
        unsigned int old = atomicAdd(&g_cnt[b], 1u);
        s_last = ((old % BLOCKS_PER_BATCH) == (BLOCKS_PER_BATCH - 1)) ? 1u : 0u;
    }
    __syncthreads();
    if (!s_last) return;
    __threadfence();                                     // acquire peers' partials

    // ======================== Phase 2: finalize batch b ========================
    const int t = threadIdx.x;
    __shared__ float sm[4], sl[4];
    __shared__ float sM, sInvL;
    __shared__ float sF[WARPS_PER_BATCH];

    float mc = -INFINITY, lc = 0.f;
    if (t < WARPS_PER_BATCH) {
        const int p = b * WARPS_PER_BATCH + t;
        mc = __ldcg(&g_m_partial[p]);
        lc = __ldcg(&g_l_partial[p]);
    }
    if (t < 128) {
        float v = mc;
#pragma unroll
        for (int o = 16; o > 0; o >>= 1)
            v = fmaxf(v, __shfl_xor_sync(0xFFFFFFFFu, v, o));
        if ((t & 31) == 0) sm[t >> 5] = v;
    }
    __syncthreads();
    if (t == 0) sM = fmaxf(fmaxf(sm[0], sm[1]), fmaxf(sm[2], sm[3]));
    __syncthreads();
    const float M = sM;
    if (t < 128) {
        float s = lc * __expf(mc - M);                   // idle slots add 0
#pragma unroll
        for (int o = 16; o > 0; o >>= 1)
            s += __shfl_xor_sync(0xFFFFFFFFu, s, o);
        if ((t & 31) == 0) sl[t >> 5] = s;
    }
    __syncthreads();
    if (t == 0) sInvL = 1.f / (sl[0] + sl[1] + sl[2] + sl[3]);
    __syncthreads();
    const float invL = sInvL;
    if (t < WARPS_PER_BATCH) sF[t] = __expf(mc - M) * invL;
    __syncthreads();

    // --- normalize weights of batch b: 1024 float4, 4 per thread ---
    {
        float4* wv = reinterpret_cast<float4*>(out_weights + (size_t)b * S);
#pragma unroll
        for (int k = 0; k < 4; ++k) {
            const int idx = t + 256 * k;
            float4 s = __ldcg(&wv[idx]);
            s.x = __expf(s.x - M) * invL;
            s.y = __expf(s.y - M) * invL;
            s.z = __expf(s.z - M) * invL;
            s.w = __expf(s.w - M) * invL;
            wv[idx] = s;
        }
    }

    // --- combine context: thread t owns float4 element t (256 of H/4) ---
    {
        const size_t pbase = (size_t)b * WARPS_PER_BATCH * (H / 4) + t;
        float4 a0 = make_float4(0.f, 0.f, 0.f, 0.f);
        float4 a1 = make_float4(0.f, 0.f, 0.f, 0.f);
        float4 a2 = make_float4(0.f, 0.f, 0.f, 0.f);
        float4 a3 = make_float4(0.f, 0.f, 0.f, 0.f);
#pragma unroll
        for (int i4 = 0; i4 < WARPS_PER_BATCH; i4 += 4) {   // 72 = 18*4
            float4 v0 = __ldcg(&g_ctx_partial[pbase + (size_t)(i4 + 0) * (H / 4)]);
            float4 v1 = __ldcg(&g_ctx_partial[pbase + (size_t)(i4 + 1) * (H / 4)]);
            float4 v2 = __ldcg(&g_ctx_partial[pbase + (size_t)(i4 + 2) * (H / 4)]);
            float4 v3 = __ldcg(&g_ctx_partial[pbase + (size_t)(i4 + 3) * (H / 4)]);
            const float f0 = sF[i4 + 0], f1 = sF[i4 + 1];
            const float f2 = sF[i4 + 2], f3 = sF[i4 + 3];
            a0.x = fmaf(f0, v0.x, a0.x); a0.y = fmaf(f0, v0.y, a0.y);
            a0.z = fmaf(f0, v0.z, a0.z); a0.w = fmaf(f0, v0.w, a0.w);
            a1.x = fmaf(f1, v1.x, a1.x); a1.y = fmaf(f1, v1.y, a1.y);
            a1.z = fmaf(f1, v1.z, a1.z); a1.w = fmaf(f1, v1.w, a1.w);
            a2.x = fmaf(f2, v2.x, a2.x); a2.y = fmaf(f2, v2.y, a2.y);
            a2.z = fmaf(f2, v2.z, a2.z); a2.w = fmaf(f2, v2.w, a2.w);
            a3.x = fmaf(f3, v3.x, a3.x); a3.y = fmaf(f3, v3.y, a3.y);
            a3.z = fmaf(f3, v3.z, a3.z); a3.w = fmaf(f3, v3.w, a3.w);
        }
        a0.x += a1.x + a2.x + a3.x;
        a0.y += a1.y + a2.y + a3.y;
        a0.z += a1.z + a2.z + a3.z;
        a0.w += a1.w + a2.w + a3.w;
        reinterpret_cast<float4*>(out_ctx)[b * (H / 4) + t] = a0;
    }
}

extern "C" void kernel_launch(void* const* d_in, const int* in_sizes, int n_in,
                              void* d_out, int out_size)
{
    const float* query = (const float*)d_in[0];   // (32,1,1024)
    const float* keys  = (const float*)d_in[1];   // (32,4096,1024)
    float* out = (float*)d_out;
    float* out_ctx = out;                  // (B,H)
    float* out_w   = out + (size_t)B * H;  // (B,S)

    cudaFuncSetAttribute(attn_fused,
                         cudaFuncAttributeMaxDynamicSharedMemorySize, SMEM_BYTES);
    attn_fused<<<NBLOCKS, THREADS, SMEM_BYTES>>>(query, keys, out_ctx, out_w);
}

// round 14
// speedup vs baseline: 1.0586x; 1.0586x over previous
#include <cuda_runtime.h>
#include <math.h>

#define B 32
#define S 4096
#define H 1024
#define WARPS_PER_BLOCK 4
#define THREADS (WARPS_PER_BLOCK * 32)          // 128
#define NBLOCKS 432                             // <=3/SM on 148 SMs, single wave
#define NWARPS (NBLOCKS * WARPS_PER_BLOCK)      // 1728
#define WARPS_PER_BATCH (NWARPS / B)            // 54
#define ROWS_BASE (S / WARPS_PER_BATCH)         // 75
#define ROWS_REM (S % WARPS_PER_BATCH)          // 46 (first 46 slots do 76 rows)

// Scratch (__device__ globals; no dynamic allocation allowed)
__device__ float4 g_ctx_partial[B * WARPS_PER_BATCH * (H / 4)];  // 6.75 MB
__device__ float  g_m_partial[B * WARPS_PER_BATCH];
__device__ float  g_l_partial[B * WARPS_PER_BATCH];
__device__ unsigned int g_cnt[B];   // per-batch warp-arrival counters (epoch via %54)

// ---------------------------------------------------------------------------
// One kernel, 128-thr blocks, 3 blocks/SM.
// Streaming: register double-buffer — next row's 8 LDG.128 issued before the
// current row's serial phase (shfl reduce + exp), keeping loads in flight.
// Finalize: the 54th-arriving WARP of each batch finalizes that batch alone.
// ---------------------------------------------------------------------------
__global__ __launch_bounds__(THREADS, 3)
void attn_fused(const float* __restrict__ query,
                const float* __restrict__ keys,
                float* __restrict__ out_ctx,
                float* __restrict__ out_weights)
{
    const int w    = threadIdx.x >> 5;
    const int lane = threadIdx.x & 31;
    const int wg   = blockIdx.x * WARPS_PER_BLOCK + w;
    const int b    = wg / WARPS_PER_BATCH;
    const int i    = wg % WARPS_PER_BATCH;
    const int start = i * ROWS_BASE + (i < ROWS_REM ? i : ROWS_REM);
    const int count = ROWS_BASE + (i < ROWS_REM ? 1 : 0);

    const float4* q4 = reinterpret_cast<const float4*>(query + (size_t)b * H);
    float4 qv[8];
#pragma unroll
    for (int j = 0; j < 8; ++j) qv[j] = q4[lane + 32 * j];

    float4 acc[8];
#pragma unroll
    for (int j = 0; j < 8; ++j) acc[j] = make_float4(0.f, 0.f, 0.f, 0.f);
    float m = -INFINITY;
    float l = 0.f;

    const float4* krow = reinterpret_cast<const float4*>(keys + ((size_t)b * S + start) * H);
    float* wout = out_weights + (size_t)b * S + start;

    float4 ka[8], kb[8];
#pragma unroll
    for (int j = 0; j < 8; ++j) ka[j] = krow[lane + 32 * j];

    // macro-free inline processing of one row held in registers `kr`,
    // while the other buffer's loads are already in flight.
#define PROCESS_ROW(kr, r)                                              \
    {                                                                   \
        float d = 0.f;                                                  \
        _Pragma("unroll")                                               \
        for (int j = 0; j < 8; ++j) {                                   \
            d = fmaf(qv[j].x, kr[j].x, d);                              \
            d = fmaf(qv[j].y, kr[j].y, d);                              \
            d = fmaf(qv[j].z, kr[j].z, d);                              \
            d = fmaf(qv[j].w, kr[j].w, d);                              \
        }                                                               \
        _Pragma("unroll")                                               \
        for (int o = 16; o > 0; o >>= 1)                                \
            d += __shfl_xor_sync(0xFFFFFFFFu, d, o);                    \
        if (lane == 0) wout[r] = d;                                     \
        float p;                                                        \
        if (d > m) {                                                    \
            float scale = __expf(m - d);                                \
            _Pragma("unroll")                                           \
            for (int j = 0; j < 8; ++j) {                               \
                acc[j].x *= scale; acc[j].y *= scale;                   \
                acc[j].z *= scale; acc[j].w *= scale;                   \
            }                                                           \
            l = fmaf(l, scale, 1.f);                                    \
            m = d;                                                      \
            p = 1.f;                                                    \
        } else {                                                        \
            p = __expf(d - m);                                          \
            l += p;                                                     \
        }                                                               \
        _Pragma("unroll")                                               \
        for (int j = 0; j < 8; ++j) {                                   \
            acc[j].x = fmaf(p, kr[j].x, acc[j].x);                      \
            acc[j].y = fmaf(p, kr[j].y, acc[j].y);                      \
            acc[j].z = fmaf(p, kr[j].z, acc[j].z);                      \
            acc[j].w = fmaf(p, kr[j].w, acc[j].w);                      \
        }                                                               \
    }

    int r = 0;
    while (r < count) {
        // even step: prefetch into kb, process ka
        if (r + 1 < count) {
            const float4* nk = krow + (size_t)(r + 1) * (H / 4);
#pragma unroll
            for (int j = 0; j < 8; ++j) kb[j] = nk[lane + 32 * j];
        }
        PROCESS_ROW(ka, r);
        ++r;
        if (r >= count) break;
        // odd step: prefetch into ka, process kb
        if (r + 1 < count) {
            const float4* nk = krow + (size_t)(r + 1) * (H / 4);
#pragma unroll
            for (int j = 0; j < 8; ++j) ka[j] = nk[lane + 32 * j];
        }
        PROCESS_ROW(kb, r);
        ++r;
    }
#undef PROCESS_ROW

    // store partials (batch-contiguous)
    const int pslot = b * WARPS_PER_BATCH + i;
    {
        float4* dst = &g_ctx_partial[(size_t)pslot * (H / 4)];
#pragma unroll
        for (int j = 0; j < 8; ++j) dst[lane + 32 * j] = acc[j];
        if (lane == 0) {
            g_m_partial[pslot] = m;
            g_l_partial[pslot] = l;
        }
    }

    // ============ warp-granular arrival; last warp finalizes batch ============
    unsigned int last = 0;
    if (lane == 0) {
        __threadfence();                       // release my partials
        unsigned int old = atomicAdd(&g_cnt[b], 1u);
        last = ((old % WARPS_PER_BATCH) == (WARPS_PER_BATCH - 1)) ? 1u : 0u;
    }
    last = __shfl_sync(0xFFFFFFFFu, last, 0);
    if (!last) return;
    __threadfence();                           // acquire peers' partials

    // ---- single-warp finalize of batch b ----
    // stats over 54 (m,l) pairs: lane holds slots lane and lane+32
    const int base = b * WARPS_PER_BATCH;
    float m0 = (lane < WARPS_PER_BATCH) ? g_m_partial[base + lane] : -INFINITY;
    float l0 = (lane < WARPS_PER_BATCH) ? g_l_partial[base + lane] : 0.f;
    float m1 = (lane + 32 < WARPS_PER_BATCH) ? g_m_partial[base + lane + 32] : -INFINITY;
    float l1 = (lane + 32 < WARPS_PER_BATCH) ? g_l_partial[base + lane + 32] : 0.f;

    float M = fmaxf(m0, m1);
#pragma unroll
    for (int o = 16; o > 0; o >>= 1)
        M = fmaxf(M, __shfl_xor_sync(0xFFFFFFFFu, M, o));

    float s = l0 * __expf(m0 - M) + l1 * __expf(m1 - M);
#pragma unroll
    for (int o = 16; o > 0; o >>= 1)
        s += __shfl_xor_sync(0xFFFFFFFFu, s, o);
    const float invL = 1.f / s;

    // normalize weights of batch b: 1024 float4, 32 per lane
    {
        float4* wv = reinterpret_cast<float4*>(out_weights + (size_t)b * S);
#pragma unroll 8
        for (int k = 0; k < 32; ++k) {
            const int idx = lane + 32 * k;
            float4 sv = __ldcg(&wv[idx]);
            sv.x = __expf(sv.x - M) * invL;
            sv.y = __expf(sv.y - M) * invL;
            sv.z = __expf(sv.z - M) * invL;
            sv.w = __expf(sv.w - M) * invL;
            wv[idx] = sv;
        }
    }

    // combine context: lane owns float4 elements lane + 32*jj (jj=0..7)
    {
        float4 c[8];
#pragma unroll
        for (int jj = 0; jj < 8; ++jj) c[jj] = make_float4(0.f, 0.f, 0.f, 0.f);

        for (int ii = 0; ii < WARPS_PER_BATCH; ++ii) {
            // factor for slot ii, from regs via shfl (no reload)
            float mi = (ii < 32) ? __shfl_sync(0xFFFFFFFFu, m0, ii)
                                 : __shfl_sync(0xFFFFFFFFu, m1, ii - 32);
            const float f = __expf(mi - M) * invL;
            const float4* src = &g_ctx_partial[(size_t)(base + ii) * (H / 4)];
#pragma unroll
            for (int jj = 0; jj < 8; ++jj) {
                float4 v = __ldcg(&src[lane + 32 * jj]);
                c[jj].x = fmaf(f, v.x, c[jj].x);
                c[jj].y = fmaf(f, v.y, c[jj].y);
                c[jj].z = fmaf(f, v.z, c[jj].z);
                c[jj].w = fmaf(f, v.w, c[jj].w);
            }
        }
        float4* oc = reinterpret_cast<float4*>(out_ctx + (size_t)b * H);
#pragma unroll
        for (int jj = 0; jj < 8; ++jj) oc[lane + 32 * jj] = c[jj];
    }
}

extern "C" void kernel_launch(void* const* d_in, const int* in_sizes, int n_in,
                              void* d_out, int out_size)
{
    const float* query = (const float*)d_in[0];   // (32,1,1024)
    const float* keys  = (const float*)d_in[1];   // (32,4096,1024)
    float* out = (float*)d_out;
    float* out_ctx = out;                  // (B,H)
    float* out_w   = out + (size_t)B * H;  // (B,S)

    attn_fused<<<NBLOCKS, THREADS>>>(query, keys, out_ctx, out_w);
}

// round 15
// speedup vs baseline: 1.2019x; 1.1354x over previous
#include <cuda_runtime.h>
#include <math.h>

#define B 32
#define S 4096
#define H 1024
#define WARPS_PER_BLOCK 8
#define K1_THREADS (WARPS_PER_BLOCK * 32)      // 256
#define K1_BLOCKS 296                          // 2 blocks/SM on 148 SMs
#define NWARPS (K1_BLOCKS * WARPS_PER_BLOCK)   // 2368
#define WARPS_PER_BATCH (NWARPS / B)           // 74
#define ROWS_BASE (S / WARPS_PER_BATCH)        // 55
#define ROWS_REM (S % WARPS_PER_BATCH)         // 26 (first 26 warps do 56 rows)

// Scratch (__device__ globals; no dynamic allocation allowed)
__device__ float4 g_ctx_partial[NWARPS * (H / 4)];   // 9.5 MB, batch-contiguous
__device__ float  g_m_partial[NWARPS];
__device__ float  g_l_partial[NWARPS];
__device__ float  g_M[B];
__device__ float  g_invL[B];

// ---------------------------------------------------------------------------
// Kernel 1: proven streaming body (82.5us) + coalesced score stores.
// Scores buffered in a lane-selected register; one 128B store per 32 rows.
// ---------------------------------------------------------------------------
__global__ __launch_bounds__(K1_THREADS)
void k1_scores_partial_ctx(const float* __restrict__ query,
                           const float* __restrict__ keys,
                           float* __restrict__ out_weights /* raw scores */)
{
    const int wg   = blockIdx.x * WARPS_PER_BLOCK + (threadIdx.x >> 5);
    const int lane = threadIdx.x & 31;
    const int b    = wg / WARPS_PER_BATCH;
    const int i    = wg % WARPS_PER_BATCH;
    const int start = i * ROWS_BASE + (i < ROWS_REM ? i : ROWS_REM);
    const int count = ROWS_BASE + (i < ROWS_REM ? 1 : 0);

    const float4* q4 = reinterpret_cast<const float4*>(query + (size_t)b * H);
    float4 qv[8];
#pragma unroll
    for (int j = 0; j < 8; ++j) qv[j] = q4[lane + 32 * j];

    float4 acc[8];
#pragma unroll
    for (int j = 0; j < 8; ++j) acc[j] = make_float4(0.f, 0.f, 0.f, 0.f);
    float m = -INFINITY;
    float l = 0.f;
    float sc = 0.f;                      // lane-selected score buffer

    const size_t base = ((size_t)b * S + start) * H;
    float* wout = out_weights + (size_t)b * S + start;

    for (int r = 0; r < count; ++r) {
        const float4* k4 = reinterpret_cast<const float4*>(keys + base + (size_t)r * H);
        float4 kv[8];
#pragma unroll
        for (int j = 0; j < 8; ++j) kv[j] = k4[lane + 32 * j];

        float d = 0.f;
#pragma unroll
        for (int j = 0; j < 8; ++j) {
            d = fmaf(qv[j].x, kv[j].x, d);
            d = fmaf(qv[j].y, kv[j].y, d);
            d = fmaf(qv[j].z, kv[j].z, d);
            d = fmaf(qv[j].w, kv[j].w, d);
        }
#pragma unroll
        for (int o = 16; o > 0; o >>= 1)
            d += __shfl_xor_sync(0xFFFFFFFFu, d, o);

        // buffer the score; flush one coalesced 128B line every 32 rows
        if ((r & 31) == lane) sc = d;
        if ((r & 31) == 31) wout[(r & ~31) + lane] = sc;

        float p;
        if (d > m) {                       // warp-uniform branch
            float scale = __expf(m - d);   // first iter: exp(-inf)=0
#pragma unroll
            for (int j = 0; j < 8; ++j) {
                acc[j].x *= scale; acc[j].y *= scale;
                acc[j].z *= scale; acc[j].w *= scale;
            }
            l = fmaf(l, scale, 1.f);
            m = d;
            p = 1.f;
        } else {
            p = __expf(d - m);
            l += p;
        }
#pragma unroll
        for (int j = 0; j < 8; ++j) {
            acc[j].x = fmaf(p, kv[j].x, acc[j].x);
            acc[j].y = fmaf(p, kv[j].y, acc[j].y);
            acc[j].z = fmaf(p, kv[j].z, acc[j].z);
            acc[j].w = fmaf(p, kv[j].w, acc[j].w);
        }
    }

    // flush score tail (count % 32 leftover rows)
    {
        const int rem = count & 31;
        if (rem && lane < rem) wout[(count & ~31) + lane] = sc;
    }

    float4* dst = &g_ctx_partial[(size_t)wg * (H / 4)];
#pragma unroll
    for (int j = 0; j < 8; ++j) dst[lane + 32 * j] = acc[j];
    if (lane == 0) {
        g_m_partial[wg] = m;
        g_l_partial[wg] = l;
    }
}

// ---------------------------------------------------------------------------
// Kernel 2a: one block (128 thr) per batch: M_b, 1/L_b. Zeroes out_ctx[b].
// ---------------------------------------------------------------------------
__global__ __launch_bounds__(128)
void k2a_stats(float* __restrict__ out_ctx)
{
    const int b = blockIdx.x;
    const int t = threadIdx.x;     // 0..127, slots 0..73 valid
    __shared__ float sm[4], sl[4], sM;

    float mc = -INFINITY, lc = 0.f;
    if (t < WARPS_PER_BATCH) {
        const int p = b * WARPS_PER_BATCH + t;
        mc = g_m_partial[p];
        lc = g_l_partial[p];
    }

    float4* oc = reinterpret_cast<float4*>(out_ctx + (size_t)b * H);
#pragma unroll
    for (int j = 0; j < 2; ++j)
        oc[t + 128 * j] = make_float4(0.f, 0.f, 0.f, 0.f);

    float v = mc;
#pragma unroll
    for (int o = 16; o > 0; o >>= 1)
        v = fmaxf(v, __shfl_xor_sync(0xFFFFFFFFu, v, o));
    if ((t & 31) == 0) sm[t >> 5] = v;
    __syncthreads();
    if (t == 0) sM = fmaxf(fmaxf(sm[0], sm[1]), fmaxf(sm[2], sm[3]));
    __syncthreads();
    const float M = sM;

    float s = lc * __expf(mc - M);   // idle slots contribute 0
#pragma unroll
    for (int o = 16; o > 0; o >>= 1)
        s += __shfl_xor_sync(0xFFFFFFFFu, s, o);
    if ((t & 31) == 0) sl[t >> 5] = s;
    __syncthreads();
    if (t == 0) {
        g_M[b] = M;
        g_invL[b] = 1.f / (sl[0] + sl[1] + sl[2] + sl[3]);
    }
}

// ---------------------------------------------------------------------------
// Kernel 2b: blocks 0..127 normalize weights (float4);
// blocks 128..735: (b,sub) combines 4 slots (independent loads, chain len 1)
// and atomicAdds the scaled context into out_ctx.
// ---------------------------------------------------------------------------
#define K2_THREADS 256
#define WNORM_BLOCKS ((B * S / 4) / K2_THREADS)   // 128
#define COMBINE_SPLIT 19                          // ceil(74/4)
#define SLOTS_PER_CBLOCK 4

__global__ __launch_bounds__(K2_THREADS)
void k2b_finalize(float* __restrict__ out_ctx, float* __restrict__ out_weights)
{
    if (blockIdx.x < WNORM_BLOCKS) {
        const int idx = blockIdx.x * K2_THREADS + threadIdx.x;  // float4 idx
        const int b = idx / (S / 4);
        const float M = g_M[b], invL = g_invL[b];
        float4 s = reinterpret_cast<float4*>(out_weights)[idx];
        s.x = __expf(s.x - M) * invL;
        s.y = __expf(s.y - M) * invL;
        s.z = __expf(s.z - M) * invL;
        s.w = __expf(s.w - M) * invL;
        reinterpret_cast<float4*>(out_weights)[idx] = s;
    } else {
        const int g   = blockIdx.x - WNORM_BLOCKS;   // 0..607
        const int b   = g / COMBINE_SPLIT;
        const int sub = g % COMBINE_SPLIT;
        const float M = g_M[b], invL = g_invL[b];
        const int t = threadIdx.x;                   // float4 element t of 256
        const int i0 = sub * SLOTS_PER_CBLOCK;

        const size_t pbase = (size_t)b * WARPS_PER_BATCH * (H / 4) + t;
        float4 c = make_float4(0.f, 0.f, 0.f, 0.f);
        // 4 independent loads (bounds-guarded; factors of idle slots = 0 anyway)
#pragma unroll
        for (int k = 0; k < SLOTS_PER_CBLOCK; ++k) {
            const int i = i0 + k;
            if (i < WARPS_PER_BATCH) {
                const float f = __expf(g_m_partial[b * WARPS_PER_BATCH + i] - M) * invL;
                float4 v = __ldcg(&g_ctx_partial[pbase + (size_t)i * (H / 4)]);
                c.x = fmaf(f, v.x, c.x);
                c.y = fmaf(f, v.y, c.y);
                c.z = fmaf(f, v.z, c.z);
                c.w = fmaf(f, v.w, c.w);
            }
        }
        float* o = out_ctx + (size_t)b * H + 4 * t;
        atomicAdd(o + 0, c.x);
        atomicAdd(o + 1, c.y);
        atomicAdd(o + 2, c.z);
        atomicAdd(o + 3, c.w);
    }
}

extern "C" void kernel_launch(void* const* d_in, const int* in_sizes, int n_in,
                              void* d_out, int out_size)
{
    const float* query = (const float*)d_in[0];   // (32,1,1024)
    const float* keys  = (const float*)d_in[1];   // (32,4096,1024)
    float* out = (float*)d_out;
    float* out_ctx = out;                  // (B,H)
    float* out_w   = out + (size_t)B * H;  // (B,S)

    k1_scores_partial_ctx<<<K1_BLOCKS, K1_THREADS>>>(query, keys, out_w);
    k2a_stats<<<B, 128>>>(out_ctx);
    k2b_finalize<<<WNORM_BLOCKS + B * COMBINE_SPLIT, K2_THREADS>>>(out_ctx, out_w);
}

// round 16
// speedup vs baseline: 1.2603x; 1.0487x over previous
#include <cuda_runtime.h>
#include <math.h>

#define B 32
#define S 4096
#define H 1024
#define WARPS_PER_BLOCK 8
#define THREADS (WARPS_PER_BLOCK * 32)          // 256
#define BLOCKS_PER_BATCH 9
#define NBLOCKS (B * BLOCKS_PER_BATCH)          // 288
#define WARPS_PER_BATCH (BLOCKS_PER_BATCH * WARPS_PER_BLOCK)  // 72
// rows per warp-slot: slots 0..63 get 57 rows, slots 64..71 get 56
#define ROWS_HI_START 64

// Scratch (__device__ globals; no dynamic allocation allowed)
__device__ float4 g_ctx_partial[NBLOCKS * (H / 4)];   // 1.2 MB (one per block!)
__device__ float  g_m_partial[NBLOCKS];
__device__ float  g_l_partial[NBLOCKS];
__device__ unsigned int g_cnt[B];     // per-batch arrival counters (epoch via %9)

// ---------------------------------------------------------------------------
// Single kernel.
// Phase 1: streaming (proven 81.6us body w/ coalesced score stores).
// Phase 1b: block-level combine: 8 warp partials -> 1 block partial (smem).
// Phase 2: 9th-arriving block of each batch finalizes that batch alone
//          (9 partials only; no atomics; overlaps straggler streaming).
// ---------------------------------------------------------------------------
__global__ __launch_bounds__(THREADS, 2)
void attn_fused(const float* __restrict__ query,
                const float* __restrict__ keys,
                float* __restrict__ out_ctx,
                float* __restrict__ out_weights)
{
    const int w    = threadIdx.x >> 5;
    const int lane = threadIdx.x & 31;
    const int b    = blockIdx.x / BLOCKS_PER_BATCH;
    const int jblk = blockIdx.x % BLOCKS_PER_BATCH;
    const int i    = jblk * WARPS_PER_BLOCK + w;        // slot 0..71
    const int start = i * 56 + (i < ROWS_HI_START ? i : ROWS_HI_START);
    const int count = (i < ROWS_HI_START) ? 57 : 56;

    float m = -INFINITY;
    float l = 0.f;
    float4 acc[8];
#pragma unroll
    for (int j = 0; j < 8; ++j) acc[j] = make_float4(0.f, 0.f, 0.f, 0.f);

    // ======================== Phase 1: streaming ========================
    {
        const float4* q4 = reinterpret_cast<const float4*>(query + (size_t)b * H);
        float4 qv[8];
#pragma unroll
        for (int j = 0; j < 8; ++j) qv[j] = q4[lane + 32 * j];

        const size_t base = ((size_t)b * S + start) * H;
        float* wout = out_weights + (size_t)b * S + start;
        float sc = 0.f;                  // lane-selected score buffer

        for (int r = 0; r < count; ++r) {
            const float4* k4 = reinterpret_cast<const float4*>(keys + base + (size_t)r * H);
            float4 kv[8];
#pragma unroll
            for (int j = 0; j < 8; ++j) kv[j] = k4[lane + 32 * j];

            float d = 0.f;
#pragma unroll
            for (int j = 0; j < 8; ++j) {
                d = fmaf(qv[j].x, kv[j].x, d);
                d = fmaf(qv[j].y, kv[j].y, d);
                d = fmaf(qv[j].z, kv[j].z, d);
                d = fmaf(qv[j].w, kv[j].w, d);
            }
#pragma unroll
            for (int o = 16; o > 0; o >>= 1)
                d += __shfl_xor_sync(0xFFFFFFFFu, d, o);

            // coalesced score stores: one 128B line per 32 rows
            if ((r & 31) == lane) sc = d;
            if ((r & 31) == 31) wout[(r & ~31) + lane] = sc;

            float p;
            if (d > m) {                       // warp-uniform branch
                float scale = __expf(m - d);   // first iter: exp(-inf)=0
#pragma unroll
                for (int j = 0; j < 8; ++j) {
                    acc[j].x *= scale; acc[j].y *= scale;
                    acc[j].z *= scale; acc[j].w *= scale;
                }
                l = fmaf(l, scale, 1.f);
                m = d;
                p = 1.f;
            } else {
                p = __expf(d - m);
                l += p;
            }
#pragma unroll
            for (int j = 0; j < 8; ++j) {
                acc[j].x = fmaf(p, kv[j].x, acc[j].x);
                acc[j].y = fmaf(p, kv[j].y, acc[j].y);
                acc[j].z = fmaf(p, kv[j].z, acc[j].z);
                acc[j].w = fmaf(p, kv[j].w, acc[j].w);
            }
        }

        // flush score tail
        const int rem = count & 31;
        if (rem && lane < rem) wout[(count & ~31) + lane] = sc;
    }

    // ============ Phase 1b: block combine (8 warp partials -> 1) ============
    __shared__ float s_ctx[WARPS_PER_BLOCK][H];  // 32 KB
    __shared__ float s_m[WARPS_PER_BLOCK], s_l[WARPS_PER_BLOCK];

    if (lane == 0) { s_m[w] = m; s_l[w] = l; }
    __syncthreads();

    float blk_m = s_m[0];
#pragma unroll
    for (int k = 1; k < WARPS_PER_BLOCK; ++k) blk_m = fmaxf(blk_m, s_m[k]);

    {
        const float scale = __expf(m - blk_m);
        float4* srow = reinterpret_cast<float4*>(s_ctx[w]);
#pragma unroll
        for (int j = 0; j < 8; ++j) {
            float4 a = acc[j];
            a.x *= scale; a.y *= scale; a.z *= scale; a.w *= scale;
            srow[lane + 32 * j] = a;
        }
    }
    __syncthreads();

    const int t = threadIdx.x;
    {
        float4 csum = make_float4(0.f, 0.f, 0.f, 0.f);
#pragma unroll
        for (int k = 0; k < WARPS_PER_BLOCK; ++k) {
            float4 v = reinterpret_cast<const float4*>(s_ctx[k])[t];
            csum.x += v.x; csum.y += v.y; csum.z += v.z; csum.w += v.w;
        }
        g_ctx_partial[(size_t)blockIdx.x * (H / 4) + t] = csum;
        if (t == 0) {
            float bl = 0.f;
#pragma unroll
            for (int k = 0; k < WARPS_PER_BLOCK; ++k)
                bl += s_l[k] * __expf(s_m[k] - blk_m);
            g_m_partial[blockIdx.x] = blk_m;
            g_l_partial[blockIdx.x] = bl;
        }
    }

    // =============== arrival: am I the last block of batch b? ===============
    __shared__ unsigned int s_last;
    __syncthreads();
    if (t == 0) {
        __threadfence();                                 // release my partial
        unsigned int old = atomicAdd(&g_cnt[b], 1u);
        s_last = ((old % BLOCKS_PER_BATCH) == (BLOCKS_PER_BATCH - 1)) ? 1u : 0u;
    }
    __syncthreads();
    if (!s_last) return;
    __threadfence();                                     // acquire peers' partials

    // ================== Phase 2: finalize batch b (9 partials) ==================
    __shared__ float sM, sInvL;
    __shared__ float sF[BLOCKS_PER_BATCH];

    if (t == 0) {
        float mv[BLOCKS_PER_BATCH], lv[BLOCKS_PER_BATCH];
        float M = -INFINITY;
#pragma unroll
        for (int k = 0; k < BLOCKS_PER_BATCH; ++k) {
            mv[k] = __ldcg(&g_m_partial[b * BLOCKS_PER_BATCH + k]);
            lv[k] = __ldcg(&g_l_partial[b * BLOCKS_PER_BATCH + k]);
            M = fmaxf(M, mv[k]);
        }
        float L = 0.f;
#pragma unroll
        for (int k = 0; k < BLOCKS_PER_BATCH; ++k)
            L += lv[k] * __expf(mv[k] - M);
        const float invL = 1.f / L;
        sM = M; sInvL = invL;
#pragma unroll
        for (int k = 0; k < BLOCKS_PER_BATCH; ++k)
            sF[k] = __expf(mv[k] - M) * invL;
    }
    __syncthreads();
    const float M = sM, invL = sInvL;

    // normalize weights of batch b: 1024 float4, 4 per thread
    {
        float4* wv = reinterpret_cast<float4*>(out_weights + (size_t)b * S);
#pragma unroll
        for (int k = 0; k < 4; ++k) {
            const int idx = t + 256 * k;
            float4 s = __ldcg(&wv[idx]);
            s.x = __expf(s.x - M) * invL;
            s.y = __expf(s.y - M) * invL;
            s.z = __expf(s.z - M) * invL;
            s.w = __expf(s.w - M) * invL;
            wv[idx] = s;
        }
    }

    // combine context: thread t owns float4 element t; 9 independent loads
    {
        const size_t pbase = (size_t)b * BLOCKS_PER_BATCH * (H / 4) + t;
        float4 c = make_float4(0.f, 0.f, 0.f, 0.f);
#pragma unroll
        for (int k = 0; k < BLOCKS_PER_BATCH; ++k) {
            float4 v = __ldcg(&g_ctx_partial[pbase + (size_t)k * (H / 4)]);
            const float f = sF[k];
            c.x = fmaf(f, v.x, c.x);
            c.y = fmaf(f, v.y, c.y);
            c.z = fmaf(f, v.z, c.z);
            c.w = fmaf(f, v.w, c.w);
        }
        reinterpret_cast<float4*>(out_ctx)[b * (H / 4) + t] = c;
    }
}

extern "C" void kernel_launch(void* const* d_in, const int* in_sizes, int n_in,
                              void* d_out, int out_size)
{
    const float* query = (const float*)d_in[0];   // (32,1,1024)
    const float* keys  = (const float*)d_in[1];   // (32,4096,1024)
    float* out = (float*)d_out;
    float* out_ctx = out;                  // (B,H)
    float* out_w   = out + (size_t)B * H;  // (B,S)

    attn_fused<<<NBLOCKS, THREADS>>>(query, keys, out_ctx, out_w);
}